// round 4
// baseline (speedup 1.0000x reference)
#include <cuda_runtime.h>

// TensorProduct: out = channel-mixing TP of x1 (64 scalars + 64 vectors) with
// x2 (1 scalar + 1 vector), five 64x64 weight matrices.
//
// Factorized form: per row compute 11 matvecs y = W^T x1-component (independent
// of x2), then a tiny epilogue combines with x2 (incl. cross product).
// Inner loop runs on the Blackwell packed-fp32 pipe via PTX fma.rn.f32x2,
// processing two rows per 64-bit register.

#define MULC      64
#define TILE      32          // rows per tile
#define RPAIRS    16          // row pairs per tile
#define NTHREADS  512
#define W_ELEMS   (MULC * MULC)           // 4096 per matrix
#define SMEM_W_ULL (5 * W_ELEMS)          // 20480 ull (weights duplicated)
#define SMEM_X_ULL (MULC * RPAIRS * 4)    // 4096 ull  (x tile, f32x2 pairs)
#define SMEM_BYTES ((SMEM_W_ULL + SMEM_X_ULL) * 8)   // 196608 B

__device__ __forceinline__ void ffma2(unsigned long long& c,
                                      unsigned long long a,
                                      unsigned long long b) {
    // packed fp32x2 FMA: c = a*b + c on both 32-bit halves
    asm("fma.rn.f32x2 %0, %1, %2, %0;" : "+l"(c) : "l"(a), "l"(b));
}

__device__ __forceinline__ float f2half(unsigned long long v, int hi) {
    return __uint_as_float(hi ? (unsigned)(v >> 32) : (unsigned)(v & 0xffffffffull));
}

__global__ __launch_bounds__(NTHREADS, 1)
void tp_kernel(const float* __restrict__ x1, const float* __restrict__ x2,
               const float* __restrict__ w1, const float* __restrict__ w2,
               const float* __restrict__ w3, const float* __restrict__ w4,
               const float* __restrict__ w5,
               float* __restrict__ out, int n) {
    extern __shared__ unsigned long long smem[];
    unsigned long long* wsm = smem;                       // [5][64u][64w] dup pairs
    float* xsf = (float*)(smem + SMEM_W_ULL);             // [64u][16rp][4c][2rows]
    const ulonglong2* xsm2 = (const ulonglong2*)(smem + SMEM_W_ULL);
    const ulonglong2* wsm2 = (const ulonglong2*)smem;

    const int tid  = threadIdx.x;
    const int lane = tid & 31;
    const int warp = tid >> 5;
    const int rp   = lane & 15;                 // row-pair index 0..15
    const int wg   = warp * 2 + (lane >> 4);    // w-group (2 outputs) 0..31
    const int w0   = wg * 2;

    // Load weights once, duplicated into both halves of a 64-bit word.
    const float* Wp[5] = {w1, w2, w3, w4, w5};
    for (int i = tid; i < 5 * W_ELEMS; i += NTHREADS) {
        unsigned b = __float_as_uint(Wp[i >> 12][i & (W_ELEMS - 1)]);
        wsm[i] = ((unsigned long long)b << 32) | (unsigned long long)b;
    }

    const float A0   = 0.08838834764831845f;   // sqrt(1/128)
    const float A0S3 = 0.05103103630798288f;   // sqrt(1/384) = a0/sqrt(3)
    const float A1   = 0.07216878364870323f;   // sqrt(1/192)
    const float A1R2 = 0.05103103630798288f;   // sqrt(1/384) = a1/sqrt(2)

    const int numTiles = (n + TILE - 1) / TILE;
    for (int tile = blockIdx.x; tile < numTiles; tile += gridDim.x) {
        const int row0 = tile * TILE;
        const int rowsLeft = n - row0;

        __syncthreads();  // xsm reuse fence (also orders weight staging, 1st iter)

        // ---- stage x1 tile, rearranged to [u][rowpair][{s,v0,v1,v2}] f32x2 ----
        const float* x1t = x1 + (size_t)row0 * 256;
        for (int q = tid; q < TILE * 256 / 4; q += NTHREADS) {
            int flat = q * 4;
            int row = flat >> 8, col0 = flat & 255;
            float4 v = make_float4(0.f, 0.f, 0.f, 0.f);
            if (row < rowsLeft)
                v = *(const float4*)(x1t + row * 256 + col0);
            float vv[4] = {v.x, v.y, v.z, v.w};
            int rsh = row >> 1, par = row & 1;
            #pragma unroll
            for (int e = 0; e < 4; e++) {
                int col = col0 + e;
                int u, c;
                if (col < MULC) { u = col; c = 0; }
                else { int t2 = col - MULC; u = t2 / 3; c = 1 + (t2 - u * 3); }
                xsf[(((u * RPAIRS + rsh) * 4 + c) << 1) | par] = vv[e];
            }
        }
        __syncthreads();

        // ---- 11 factorized matvecs, 2 rows packed per f32x2, 2 w per thread ----
        unsigned long long aS1[2] = {0ull, 0ull}, aV3[2] = {0ull, 0ull};
        unsigned long long aS2[2][3] = {}, aV4[2][3] = {}, aV5[2][3] = {};

        #pragma unroll 4
        for (int u = 0; u < MULC; u++) {
            ulonglong2 xa = xsm2[(u * RPAIRS + rp) * 2];      // xs | xv0
            ulonglong2 xb = xsm2[(u * RPAIRS + rp) * 2 + 1];  // xv1 | xv2
            ulonglong2 W1 = wsm2[(0 * MULC + u) * 32 + wg];
            ulonglong2 W2 = wsm2[(1 * MULC + u) * 32 + wg];
            ulonglong2 W3 = wsm2[(2 * MULC + u) * 32 + wg];
            ulonglong2 W4 = wsm2[(3 * MULC + u) * 32 + wg];
            ulonglong2 W5 = wsm2[(4 * MULC + u) * 32 + wg];

            ffma2(aS1[0], W1.x, xa.x);  ffma2(aS1[1], W1.y, xa.x);
            ffma2(aV3[0], W3.x, xa.x);  ffma2(aV3[1], W3.y, xa.x);

            ffma2(aS2[0][0], W2.x, xa.y);  ffma2(aS2[1][0], W2.y, xa.y);
            ffma2(aS2[0][1], W2.x, xb.x);  ffma2(aS2[1][1], W2.y, xb.x);
            ffma2(aS2[0][2], W2.x, xb.y);  ffma2(aS2[1][2], W2.y, xb.y);

            ffma2(aV4[0][0], W4.x, xa.y);  ffma2(aV4[1][0], W4.y, xa.y);
            ffma2(aV4[0][1], W4.x, xb.x);  ffma2(aV4[1][1], W4.y, xb.x);
            ffma2(aV4[0][2], W4.x, xb.y);  ffma2(aV4[1][2], W4.y, xb.y);

            ffma2(aV5[0][0], W5.x, xa.y);  ffma2(aV5[1][0], W5.y, xa.y);
            ffma2(aV5[0][1], W5.x, xb.x);  ffma2(aV5[1][1], W5.y, xb.x);
            ffma2(aV5[0][2], W5.x, xb.y);  ffma2(aV5[1][2], W5.y, xb.y);
        }

        // ---- epilogue: combine with x2, incl. cross(y5, x2v) ----
        #pragma unroll
        for (int p = 0; p < 2; p++) {
            int row = row0 + rp * 2 + p;
            if (row >= n) continue;
            float s  = x2[row * 4 + 0];
            float v0 = x2[row * 4 + 1];
            float v1 = x2[row * 4 + 2];
            float v2 = x2[row * 4 + 3];
            float* o = out + (size_t)row * 256;
            #pragma unroll
            for (int j = 0; j < 2; j++) {
                int w = w0 + j;
                float y1  = f2half(aS1[j], p);
                float y20 = f2half(aS2[j][0], p), y21 = f2half(aS2[j][1], p), y22 = f2half(aS2[j][2], p);
                float y3  = f2half(aV3[j], p);
                float y40 = f2half(aV4[j][0], p), y41 = f2half(aV4[j][1], p), y42 = f2half(aV4[j][2], p);
                float y50 = f2half(aV5[j][0], p), y51 = f2half(aV5[j][1], p), y52 = f2half(aV5[j][2], p);

                float os = A0 * s * y1 + A0S3 * (v0 * y20 + v1 * y21 + v2 * y22);
                float c0 = y51 * v2 - y52 * v1;
                float c1 = y52 * v0 - y50 * v2;
                float c2 = y50 * v1 - y51 * v0;

                o[w] = os;
                o[64 + 3 * w + 0] = A1 * (v0 * y3 + s * y40) + A1R2 * c0;
                o[64 + 3 * w + 1] = A1 * (v1 * y3 + s * y41) + A1R2 * c1;
                o[64 + 3 * w + 2] = A1 * (v2 * y3 + s * y42) + A1R2 * c2;
            }
        }
    }
}

extern "C" void kernel_launch(void* const* d_in, const int* in_sizes, int n_in,
                              void* d_out, int out_size) {
    const float* x1 = (const float*)d_in[0];
    const float* x2 = (const float*)d_in[1];
    const float* w1 = (const float*)d_in[2];   // w_ss_s
    const float* w2 = (const float*)d_in[3];   // w_vv_s
    const float* w3 = (const float*)d_in[4];   // w_sv_v
    const float* w4 = (const float*)d_in[5];   // w_vs_v
    const float* w5 = (const float*)d_in[6];   // w_vv_v
    float* out = (float*)d_out;

    int n = in_sizes[0] / 256;
    cudaFuncSetAttribute(tp_kernel, cudaFuncAttributeMaxDynamicSharedMemorySize,
                         SMEM_BYTES);
    int numTiles = (n + TILE - 1) / TILE;
    int grid = numTiles < 148 ? numTiles : 148;   // persistent, 1 CTA/SM
    tp_kernel<<<grid, NTHREADS, SMEM_BYTES>>>(x1, x2, w1, w2, w3, w4, w5, out, n);
}

// round 5
// speedup vs baseline: 3.5709x; 3.5709x over previous
#include <cuda_runtime.h>
#include <cstdint>

// TensorProduct via x2-folded tf32 GEMMs.
//
//   out_s (n,64)      = A_s (n,128)  @ B_s (128,64)
//   out_v[:, :, k]    = A_vk (n,192) @ B_v (192,64)   k=0,1,2  (B_v shared)
// with per-row A built from x1,x2 elementwise:
//   A_s  = [ x1s*x2s           | dot(x1v,x2v) ]
//   A_vk = [ x1s*x2v_k | x1v_k*x2s | cross(x1v,x2v)_k ]
// Scales folded into B. GEMMs run on mma.sync.m16n8k8 tf32 (fp32 accum).

#define NTHREADS 512
#define TILE     32

// smem row strides in 32-bit words (pad +8 words = 32B -> conflict-free frags)
#define RS_AS 136    // 128 + 8
#define RS_AV 200    // 192 + 8
#define RS_BS 136
#define RS_BV 200
#define RS_O  264    // 256 + 8

#define OFF_BS 0
#define OFF_BV (OFF_BS + 64 * RS_BS)      //  8704
#define OFF_AS (OFF_BV + 64 * RS_BV)      // 21504
#define OFF_AV (OFF_AS + TILE * RS_AS)    // 25856
#define AV_SZ  (TILE * RS_AV)             //  6400
#define OFF_O  (OFF_AV + 3 * AV_SZ)       // 45056
#define SMEM_WORDS (OFF_O + TILE * RS_O)  // 53504
#define SMEM_BYTES (SMEM_WORDS * 4)       // 214016 B

__device__ __forceinline__ uint32_t tf32(float f) {
    uint32_t u; asm("cvt.rna.tf32.f32 %0, %1;" : "=r"(u) : "f"(f)); return u;
}

// depth swizzle within a row: element K lands so that a thread's {K, K+4}
// fragment pair is one aligned 8-byte load.
__device__ __forceinline__ int swz(int K) {
    return ((K >> 3) << 3) + ((K & 3) << 1) + ((K >> 2) & 1);
}

__device__ __forceinline__ void mma8(float* c, uint32_t a0, uint32_t a1,
                                     uint32_t a2, uint32_t a3,
                                     uint32_t b0, uint32_t b1) {
    asm volatile(
        "mma.sync.aligned.m16n8k8.row.col.f32.tf32.tf32.f32 "
        "{%0,%1,%2,%3}, {%4,%5,%6,%7}, {%8,%9}, {%0,%1,%2,%3};"
        : "+f"(c[0]), "+f"(c[1]), "+f"(c[2]), "+f"(c[3])
        : "r"(a0), "r"(a1), "r"(a2), "r"(a3), "r"(b0), "r"(b1));
}

__global__ __launch_bounds__(NTHREADS, 1)
void tp_mma_kernel(const float* __restrict__ x1, const float* __restrict__ x2,
                   const float* __restrict__ w1, const float* __restrict__ w2,
                   const float* __restrict__ w3, const float* __restrict__ w4,
                   const float* __restrict__ w5,
                   float* __restrict__ out, int n) {
    extern __shared__ uint32_t sm[];
    float* osm = (float*)(sm + OFF_O);
    const int tid  = threadIdx.x;
    const int lane = tid & 31;
    const int wid  = tid >> 5;

    const float A0   = 0.08838834764831845f;   // sqrt(1/128)
    const float A0S3 = 0.05103103630798288f;   // a0/sqrt(3)
    const float A1   = 0.07216878364870323f;   // sqrt(1/192)
    const float A1R2 = 0.05103103630798288f;   // a1/sqrt(2)

    // ---- stage B once (scales folded in, tf32-rounded, swizzled, n-major) ----
    for (int idx = tid; idx < 128 * 64; idx += NTHREADS) {
        int K = idx >> 6, w = idx & 63;
        float v = (K < 64) ? A0 * w1[K * 64 + w] : A0S3 * w2[(K - 64) * 64 + w];
        sm[OFF_BS + w * RS_BS + swz(K)] = tf32(v);
    }
    for (int idx = tid; idx < 192 * 64; idx += NTHREADS) {
        int K = idx >> 6, w = idx & 63;
        float v = (K < 64)  ? A1 * w3[K * 64 + w]
                : (K < 128) ? A1 * w4[(K - 64) * 64 + w]
                :             A1R2 * w5[(K - 128) * 64 + w];
        sm[OFF_BV + w * RS_BV + swz(K)] = tf32(v);
    }

    // ---- warp roles: 2 row-slabs x 8 column-groups ----
    const int slab = wid >> 3;          // 0..1 -> rows slab*16
    const int g    = wid & 7;           // 0,1: GEMM_s halves; 2..7: GEMM_v (k,half)
    const int row0loc = slab * 16;
    int ksteps, rsA, rsB, wbase, kv = 0, aOff;
    const uint32_t* Bw;
    if (g < 2) {
        aOff = OFF_AS; Bw = sm + OFF_BS; ksteps = 16;
        rsA = RS_AS; rsB = RS_BS; wbase = g * 32;
    } else {
        kv = (g - 2) >> 1; int h = (g - 2) & 1;
        aOff = OFF_AV + kv * AV_SZ; Bw = sm + OFF_BV; ksteps = 24;
        rsA = RS_AV; rsB = RS_BV; wbase = h * 32;
    }
    const uint32_t* bP = Bw + (wbase + (lane >> 2)) * rsB + (lane & 3) * 2;

    const int numTiles = (n + TILE - 1) / TILE;
    for (int tile = blockIdx.x; tile < numTiles; tile += gridDim.x) {
        const int row0 = tile * TILE;
        __syncthreads();   // previous tile fully consumed (A, osm reusable)

        // ---- stage A: fold x2 into x1 features, tf32, swizzled ----
        #pragma unroll
        for (int it = 0; it < 4; it++) {
            int cell = tid + it * NTHREADS;          // 2048 = 32 rows x 64 u
            int r = cell >> 6, u = cell & 63;
            int row = row0 + r;
            float s = 0.f, v0 = 0.f, v1 = 0.f, v2 = 0.f;
            float xs = 0.f, y0 = 0.f, y1 = 0.f, y2 = 0.f;
            if (row < n) {
                const float* xp = x1 + (size_t)row * 256;
                s = xp[u];
                const float* vp = xp + 64 + 3 * u;
                v0 = vp[0]; v1 = vp[1]; v2 = vp[2];
                const float* x2p = x2 + (size_t)row * 4;
                xs = x2p[0]; y0 = x2p[1]; y1 = x2p[2]; y2 = x2p[3];
            }
            uint32_t* As = sm + OFF_AS + r * RS_AS;
            As[swz(u)]      = tf32(s * xs);
            As[swz(64 + u)] = tf32(v0 * y0 + v1 * y1 + v2 * y2);
            uint32_t* Av0 = sm + OFF_AV + r * RS_AV;
            Av0[swz(u)]       = tf32(s * y0);
            Av0[swz(64 + u)]  = tf32(v0 * xs);
            Av0[swz(128 + u)] = tf32(v1 * y2 - v2 * y1);
            uint32_t* Av1 = Av0 + AV_SZ;
            Av1[swz(u)]       = tf32(s * y1);
            Av1[swz(64 + u)]  = tf32(v1 * xs);
            Av1[swz(128 + u)] = tf32(v2 * y0 - v0 * y2);
            uint32_t* Av2 = Av1 + AV_SZ;
            Av2[swz(u)]       = tf32(s * y2);
            Av2[swz(64 + u)]  = tf32(v2 * xs);
            Av2[swz(128 + u)] = tf32(v0 * y1 - v1 * y0);
        }
        __syncthreads();

        // ---- mma mainloop: 4 n8-tiles per warp ----
        float acc[4][4];
        #pragma unroll
        for (int t = 0; t < 4; t++)
            #pragma unroll
            for (int c = 0; c < 4; c++) acc[t][c] = 0.f;

        const uint32_t* aP = sm + aOff + (row0loc + (lane >> 2)) * rsA
                           + (lane & 3) * 2;
        #pragma unroll 8
        for (int ks = 0; ks < ksteps; ks++) {
            uint2 alo = *(const uint2*)(aP + ks * 8);            // a0,a2
            uint2 ahi = *(const uint2*)(aP + 8 * rsA + ks * 8);  // a1,a3
            #pragma unroll
            for (int t = 0; t < 4; t++) {
                uint2 b = *(const uint2*)(bP + t * 8 * rsB + ks * 8);
                mma8(acc[t], alo.x, ahi.x, alo.y, ahi.y, b.x, b.y);
            }
        }

        // ---- scatter accums into out-layout smem ----
        {
            int r1 = row0loc + (lane >> 2);
            if (g < 2) {
                #pragma unroll
                for (int t = 0; t < 4; t++) {
                    int w = wbase + t * 8 + ((lane & 3) << 1);
                    *(float2*)&osm[r1 * RS_O + w] =
                        make_float2(acc[t][0], acc[t][1]);
                    *(float2*)&osm[(r1 + 8) * RS_O + w] =
                        make_float2(acc[t][2], acc[t][3]);
                }
            } else {
                #pragma unroll
                for (int t = 0; t < 4; t++) {
                    int w = wbase + t * 8 + ((lane & 3) << 1);
                    osm[r1 * RS_O + 64 + 3 * w + kv]           = acc[t][0];
                    osm[r1 * RS_O + 64 + 3 * (w + 1) + kv]     = acc[t][1];
                    osm[(r1 + 8) * RS_O + 64 + 3 * w + kv]     = acc[t][2];
                    osm[(r1 + 8) * RS_O + 64 + 3 * (w + 1) + kv] = acc[t][3];
                }
            }
        }
        __syncthreads();

        // ---- coalesced store: osm -> out ----
        #pragma unroll
        for (int it = 0; it < 4; it++) {
            int idx = tid + it * NTHREADS;        // 2048 float4 cells
            int r = idx >> 6, c4 = (idx & 63) << 2;
            int row = row0 + r;
            if (row < n)
                *(float4*)(out + (size_t)row * 256 + c4) =
                    *(const float4*)(osm + r * RS_O + c4);
        }
    }
}

extern "C" void kernel_launch(void* const* d_in, const int* in_sizes, int n_in,
                              void* d_out, int out_size) {
    const float* x1 = (const float*)d_in[0];
    const float* x2 = (const float*)d_in[1];
    const float* w1 = (const float*)d_in[2];   // w_ss_s
    const float* w2 = (const float*)d_in[3];   // w_vv_s
    const float* w3 = (const float*)d_in[4];   // w_sv_v
    const float* w4 = (const float*)d_in[5];   // w_vs_v
    const float* w5 = (const float*)d_in[6];   // w_vv_v
    float* out = (float*)d_out;

    int n = in_sizes[0] / 256;
    cudaFuncSetAttribute(tp_mma_kernel,
                         cudaFuncAttributeMaxDynamicSharedMemorySize, SMEM_BYTES);
    int numTiles = (n + TILE - 1) / TILE;
    int grid = numTiles < 148 ? numTiles : 148;
    tp_mma_kernel<<<grid, NTHREADS, SMEM_BYTES>>>(x1, x2, w1, w2, w3, w4, w5,
                                                  out, n);
}